// round 4
// baseline (speedup 1.0000x reference)
#include <cuda_runtime.h>
#include <cstdint>

#define B_     2
#define NRES   2048
#define NATOM  16384
#define CS     384
#define COUT   50
#define OPAD   64
#define KT     64
#define RPB    32
#define GEMM_BLOCKS ((B_ * NRES) / RPB)   // 128
#define SCAN_BLOCKS ((B_ * NATOM) / 8)    // 4096

// Scratch + sync state (all left at initial values at kernel exit -> replay-safe)
__device__ float g_res_logits[B_ * NRES * COUT];   // 3.2 MB
__device__ int   g_done    = 0;                    // GEMM blocks completed
__device__ int   g_scanfin = 0;                    // scan blocks completed

// ---------------------------------------------------------------------------
// Single fused kernel:
//   blocks [0, 128):     GEMM res_logits = s @ W^T + b, then signal g_done.
//   blocks [128, 4224):  warp-per-atom one-hot scan (early exit), wait for
//                        g_done==128, gather res_logits row -> out.
// Last scan block resets counters for the next graph replay.
// ---------------------------------------------------------------------------
__global__ void __launch_bounds__(256)
fused_kernel(const float* __restrict__ s,     // [B, NRES, CS]
             const float* __restrict__ tta,   // [B, NATOM, NRES]
             const float* __restrict__ W,     // [COUT, CS]
             const float* __restrict__ bias,  // [COUT]
             float* __restrict__ out)         // [B, NATOM, COUT]
{
    __shared__ float s_sm[RPB][KT];     // 8 KB
    __shared__ float wt_sm[KT][OPAD];   // 16 KB (24 KB total)

    const int tid = threadIdx.x;

    if (blockIdx.x < GEMM_BLOCKS) {
        // ----------------- GEMM branch -----------------
        const int to  = tid & 15;
        const int tr  = tid >> 4;
        const int o0  = to << 2;
        const int r0  = tr << 1;
        const int r1  = r0 + 1;
        const int row0 = blockIdx.x * RPB;

        const int wo = tid & 63;          // out channel for W transpose loads
        const int wg = tid >> 6;          // k-group 0..3

        float4 accA = make_float4(0.f, 0.f, 0.f, 0.f);
        float4 accB = make_float4(0.f, 0.f, 0.f, 0.f);

        for (int kt = 0; kt < CS; kt += KT) {
            {   // s tile: 32 rows x 64 k = 512 float4, coalesced
                const float4* __restrict__ sg = reinterpret_cast<const float4*>(s);
                float4* s4 = reinterpret_cast<float4*>(&s_sm[0][0]);
                #pragma unroll
                for (int i = 0; i < 2; ++i) {
                    const int f = tid + 256 * i;
                    const int r = f >> 4;
                    const int c = f & 15;
                    s4[f] = sg[(size_t)(row0 + r) * (CS / 4) + (kt >> 2) + c];
                }
            }
            // W tile transposed in-smem: lanes stride o -> conflict-free STS
            #pragma unroll
            for (int m = 0; m < 4; ++m) {
                const int k0 = (wg << 4) + (m << 2);
                float4 v = make_float4(0.f, 0.f, 0.f, 0.f);
                if (wo < COUT)
                    v = *reinterpret_cast<const float4*>(&W[(size_t)wo * CS + kt + k0]);
                wt_sm[k0 + 0][wo] = v.x;
                wt_sm[k0 + 1][wo] = v.y;
                wt_sm[k0 + 2][wo] = v.z;
                wt_sm[k0 + 3][wo] = v.w;
            }
            __syncthreads();

            #pragma unroll
            for (int kk = 0; kk < KT; kk += 4) {
                const float4 sa = *reinterpret_cast<const float4*>(&s_sm[r0][kk]);
                const float4 sb = *reinterpret_cast<const float4*>(&s_sm[r1][kk]);
                const float4 w0 = *reinterpret_cast<const float4*>(&wt_sm[kk + 0][o0]);
                const float4 w1 = *reinterpret_cast<const float4*>(&wt_sm[kk + 1][o0]);
                const float4 w2 = *reinterpret_cast<const float4*>(&wt_sm[kk + 2][o0]);
                const float4 w3 = *reinterpret_cast<const float4*>(&wt_sm[kk + 3][o0]);

                accA.x = fmaf(sa.x, w0.x, accA.x); accA.y = fmaf(sa.x, w0.y, accA.y);
                accA.z = fmaf(sa.x, w0.z, accA.z); accA.w = fmaf(sa.x, w0.w, accA.w);
                accB.x = fmaf(sb.x, w0.x, accB.x); accB.y = fmaf(sb.x, w0.y, accB.y);
                accB.z = fmaf(sb.x, w0.z, accB.z); accB.w = fmaf(sb.x, w0.w, accB.w);

                accA.x = fmaf(sa.y, w1.x, accA.x); accA.y = fmaf(sa.y, w1.y, accA.y);
                accA.z = fmaf(sa.y, w1.z, accA.z); accA.w = fmaf(sa.y, w1.w, accA.w);
                accB.x = fmaf(sb.y, w1.x, accB.x); accB.y = fmaf(sb.y, w1.y, accB.y);
                accB.z = fmaf(sb.y, w1.z, accB.z); accB.w = fmaf(sb.y, w1.w, accB.w);

                accA.x = fmaf(sa.z, w2.x, accA.x); accA.y = fmaf(sa.z, w2.y, accA.y);
                accA.z = fmaf(sa.z, w2.z, accA.z); accA.w = fmaf(sa.z, w2.w, accA.w);
                accB.x = fmaf(sb.z, w2.x, accB.x); accB.y = fmaf(sb.z, w2.y, accB.y);
                accB.z = fmaf(sb.z, w2.z, accB.z); accB.w = fmaf(sb.z, w2.w, accB.w);

                accA.x = fmaf(sa.w, w3.x, accA.x); accA.y = fmaf(sa.w, w3.y, accA.y);
                accA.z = fmaf(sa.w, w3.z, accA.z); accA.w = fmaf(sa.w, w3.w, accA.w);
                accB.x = fmaf(sb.w, w3.x, accB.x); accB.y = fmaf(sb.w, w3.y, accB.y);
                accB.z = fmaf(sb.w, w3.z, accB.z); accB.w = fmaf(sb.w, w3.w, accB.w);
            }
            __syncthreads();
        }

        const float aA[4] = {accA.x, accA.y, accA.z, accA.w};
        const float aB[4] = {accB.x, accB.y, accB.z, accB.w};
        #pragma unroll
        for (int c = 0; c < 4; ++c) {
            const int o = o0 + c;
            if (o < COUT) {
                const float bv = bias[o];
                g_res_logits[(size_t)(row0 + r0) * COUT + o] = aA[c] + bv;
                g_res_logits[(size_t)(row0 + r1) * COUT + o] = aB[c] + bv;
            }
        }

        // Signal: this block's res_logits rows are visible.
        __syncthreads();
        __threadfence();
        if (tid == 0) atomicAdd(&g_done, 1);
    } else {
        // ----------------- scan + gather branch: warp per atom -----------------
        const int gwarp = (blockIdx.x - GEMM_BLOCKS) * 8 + (tid >> 5);
        const int lane  = tid & 31;

        const float4* __restrict__ row =
            reinterpret_cast<const float4*>(tta + (size_t)gwarp * NRES);

        int idx = 0;
        // 512 float4 per row; rounds of 64 float4 (256 floats), 2 f4/lane
        #pragma unroll 1
        for (int r = 0; r < 8; ++r) {
            const int f0 = r * 64 + lane;
            const int f1 = f0 + 32;
            const float4 v0 = __ldcs(&row[f0]);
            const float4 v1 = __ldcs(&row[f1]);

            int my = -1;
            {
                const int jb = f1 << 2;
                if (v1.w != 0.0f) my = jb + 3;
                if (v1.z != 0.0f) my = jb + 2;
                if (v1.y != 0.0f) my = jb + 1;
                if (v1.x != 0.0f) my = jb;
            }
            {
                const int jb = f0 << 2;
                if (v0.w != 0.0f) my = jb + 3;
                if (v0.z != 0.0f) my = jb + 2;
                if (v0.y != 0.0f) my = jb + 1;
                if (v0.x != 0.0f) my = jb;
            }

            const unsigned m = __ballot_sync(0xffffffffu, my >= 0);
            if (m) {
                idx = __shfl_sync(0xffffffffu, my, __ffs(m) - 1);
                break;
            }
        }

        // Wait for GEMM completion (hidden under other warps' streaming).
        if (lane == 0) {
            while (*(volatile int*)&g_done < GEMM_BLOCKS) __nanosleep(100);
        }
        __syncwarp();
        __threadfence();   // order res_logits reads after flag observation

        const int b = gwarp >> 14;
        const float2* __restrict__ src = reinterpret_cast<const float2*>(
            g_res_logits + ((size_t)b * NRES + idx) * COUT);
        float2* __restrict__ dst = reinterpret_cast<float2*>(
            out + (size_t)gwarp * COUT);
        if (lane < COUT / 2) dst[lane] = src[lane];

        // Counter reset protocol: last scan block to finish clears both
        // counters so the next graph replay starts from a clean state.
        __syncthreads();
        if (tid == 0) {
            const int old = atomicAdd(&g_scanfin, 1);
            if (old == SCAN_BLOCKS - 1) {
                g_done    = 0;
                g_scanfin = 0;
            }
        }
    }
}

extern "C" void kernel_launch(void* const* d_in, const int* in_sizes, int n_in,
                              void* d_out, int out_size)
{
    const float* s    = (const float*)d_in[0];  // [B, NRES, CS]
    const float* tta  = (const float*)d_in[1];  // [B, NATOM, NRES]
    const float* W    = (const float*)d_in[2];  // [COUT, CS]
    const float* bias = (const float*)d_in[3];  // [COUT]
    float* out = (float*)d_out;

    (void)in_sizes; (void)n_in; (void)out_size;

    fused_kernel<<<GEMM_BLOCKS + SCAN_BLOCKS, 256>>>(s, tta, W, bias, out);
}

// round 5
// speedup vs baseline: 1.0803x; 1.0803x over previous
#include <cuda_runtime.h>
#include <cstdint>

#define B_     2
#define NRES   2048
#define NATOM  16384
#define CS     384
#define COUT   50
#define OPAD   64
#define KT     64
#define RPB    32
#define GEMM_BLOCKS ((B_ * NRES) / RPB)    // 128
#define SCAN_BLOCKS ((B_ * NATOM) / 16)    // 2048 (2 atoms per warp, 8 warps/block)

// Scratch + sync state (restored to initial values at exit -> graph-replay safe)
__device__ float g_res_logits[B_ * NRES * COUT];   // 3.2 MB
__device__ int   g_done    = 0;
__device__ int   g_scanfin = 0;

// ---------------------------------------------------------------------------
// Single fused kernel:
//   blocks [0, 128):    GEMM res_logits = s @ W^T + b, signal g_done.
//   blocks [128, 2176): warp scans TWO one-hot rows concurrently (MLP=8
//                       LDG.128), early exit per row, waits g_done==128,
//                       gathers both rows -> out.
// ---------------------------------------------------------------------------
__global__ void __launch_bounds__(256)
fused_kernel(const float* __restrict__ s,     // [B, NRES, CS]
             const float* __restrict__ tta,   // [B, NATOM, NRES]
             const float* __restrict__ W,     // [COUT, CS]
             const float* __restrict__ bias,  // [COUT]
             float* __restrict__ out)         // [B, NATOM, COUT]
{
    __shared__ float s_sm[RPB][KT];     // 8 KB
    __shared__ float wt_sm[KT][OPAD];   // 16 KB

    const int tid = threadIdx.x;

    if (blockIdx.x < GEMM_BLOCKS) {
        // ----------------- GEMM branch -----------------
        const int to  = tid & 15;
        const int tr  = tid >> 4;
        const int o0  = to << 2;
        const int r0  = tr << 1;
        const int r1  = r0 + 1;
        const int row0 = blockIdx.x * RPB;

        const int wo = tid & 63;
        const int wg = tid >> 6;

        float4 accA = make_float4(0.f, 0.f, 0.f, 0.f);
        float4 accB = make_float4(0.f, 0.f, 0.f, 0.f);

        for (int kt = 0; kt < CS; kt += KT) {
            {
                const float4* __restrict__ sg = reinterpret_cast<const float4*>(s);
                float4* s4 = reinterpret_cast<float4*>(&s_sm[0][0]);
                #pragma unroll
                for (int i = 0; i < 2; ++i) {
                    const int f = tid + 256 * i;
                    const int r = f >> 4;
                    const int c = f & 15;
                    s4[f] = sg[(size_t)(row0 + r) * (CS / 4) + (kt >> 2) + c];
                }
            }
            #pragma unroll
            for (int m = 0; m < 4; ++m) {
                const int k0 = (wg << 4) + (m << 2);
                float4 v = make_float4(0.f, 0.f, 0.f, 0.f);
                if (wo < COUT)
                    v = *reinterpret_cast<const float4*>(&W[(size_t)wo * CS + kt + k0]);
                wt_sm[k0 + 0][wo] = v.x;
                wt_sm[k0 + 1][wo] = v.y;
                wt_sm[k0 + 2][wo] = v.z;
                wt_sm[k0 + 3][wo] = v.w;
            }
            __syncthreads();

            #pragma unroll
            for (int kk = 0; kk < KT; kk += 4) {
                const float4 sa = *reinterpret_cast<const float4*>(&s_sm[r0][kk]);
                const float4 sb = *reinterpret_cast<const float4*>(&s_sm[r1][kk]);
                const float4 w0 = *reinterpret_cast<const float4*>(&wt_sm[kk + 0][o0]);
                const float4 w1 = *reinterpret_cast<const float4*>(&wt_sm[kk + 1][o0]);
                const float4 w2 = *reinterpret_cast<const float4*>(&wt_sm[kk + 2][o0]);
                const float4 w3 = *reinterpret_cast<const float4*>(&wt_sm[kk + 3][o0]);

                accA.x = fmaf(sa.x, w0.x, accA.x); accA.y = fmaf(sa.x, w0.y, accA.y);
                accA.z = fmaf(sa.x, w0.z, accA.z); accA.w = fmaf(sa.x, w0.w, accA.w);
                accB.x = fmaf(sb.x, w0.x, accB.x); accB.y = fmaf(sb.x, w0.y, accB.y);
                accB.z = fmaf(sb.x, w0.z, accB.z); accB.w = fmaf(sb.x, w0.w, accB.w);

                accA.x = fmaf(sa.y, w1.x, accA.x); accA.y = fmaf(sa.y, w1.y, accA.y);
                accA.z = fmaf(sa.y, w1.z, accA.z); accA.w = fmaf(sa.y, w1.w, accA.w);
                accB.x = fmaf(sb.y, w1.x, accB.x); accB.y = fmaf(sb.y, w1.y, accB.y);
                accB.z = fmaf(sb.y, w1.z, accB.z); accB.w = fmaf(sb.y, w1.w, accB.w);

                accA.x = fmaf(sa.z, w2.x, accA.x); accA.y = fmaf(sa.z, w2.y, accA.y);
                accA.z = fmaf(sa.z, w2.z, accA.z); accA.w = fmaf(sa.z, w2.w, accA.w);
                accB.x = fmaf(sb.z, w2.x, accB.x); accB.y = fmaf(sb.z, w2.y, accB.y);
                accB.z = fmaf(sb.z, w2.z, accB.z); accB.w = fmaf(sb.z, w2.w, accB.w);

                accA.x = fmaf(sa.w, w3.x, accA.x); accA.y = fmaf(sa.w, w3.y, accA.y);
                accA.z = fmaf(sa.w, w3.z, accA.z); accA.w = fmaf(sa.w, w3.w, accA.w);
                accB.x = fmaf(sb.w, w3.x, accB.x); accB.y = fmaf(sb.w, w3.y, accB.y);
                accB.z = fmaf(sb.w, w3.z, accB.z); accB.w = fmaf(sb.w, w3.w, accB.w);
            }
            __syncthreads();
        }

        const float aA[4] = {accA.x, accA.y, accA.z, accA.w};
        const float aB[4] = {accB.x, accB.y, accB.z, accB.w};
        #pragma unroll
        for (int c = 0; c < 4; ++c) {
            const int o = o0 + c;
            if (o < COUT) {
                const float bv = bias[o];
                g_res_logits[(size_t)(row0 + r0) * COUT + o] = aA[c] + bv;
                g_res_logits[(size_t)(row0 + r1) * COUT + o] = aB[c] + bv;
            }
        }

        __syncthreads();
        __threadfence();
        if (tid == 0) atomicAdd(&g_done, 1);
    } else {
        // -------- scan branch: 2 atoms per warp, MLP = 8 x LDG.128 --------
        const int gw   = (blockIdx.x - GEMM_BLOCKS) * 8 + (tid >> 5);
        const int lane = tid & 31;
        const int a0   = gw * 2;
        const int a1   = a0 + 1;

        const float4* __restrict__ rowA =
            reinterpret_cast<const float4*>(tta + (size_t)a0 * NRES);
        const float4* __restrict__ rowB =
            reinterpret_cast<const float4*>(tta + (size_t)a1 * NRES);

        int idx0 = -1, idx1 = -1;

        // 512 float4 per row; rounds of 128 float4 (512 floats) per row.
        #pragma unroll 1
        for (int r = 0; r < 4; ++r) {
            const bool need0 = (idx0 < 0);   // warp-uniform
            const bool need1 = (idx1 < 0);

            float4 u[4], v[4];
            if (need0) {
                #pragma unroll
                for (int j = 0; j < 4; ++j)
                    u[j] = __ldcs(&rowA[r * 128 + j * 32 + lane]);
            }
            if (need1) {
                #pragma unroll
                for (int j = 0; j < 4; ++j)
                    v[j] = __ldcs(&rowB[r * 128 + j * 32 + lane]);
            }

            if (need0) {
                int my = -1;
                #pragma unroll
                for (int j = 3; j >= 0; --j) {
                    const int jb = (r * 128 + j * 32 + lane) << 2;
                    if (u[j].w != 0.0f) my = jb + 3;
                    if (u[j].z != 0.0f) my = jb + 2;
                    if (u[j].y != 0.0f) my = jb + 1;
                    if (u[j].x != 0.0f) my = jb;
                }
                const unsigned m = __ballot_sync(0xffffffffu, my >= 0);
                if (m) idx0 = __shfl_sync(0xffffffffu, my, __ffs(m) - 1);
            }
            if (need1) {
                int my = -1;
                #pragma unroll
                for (int j = 3; j >= 0; --j) {
                    const int jb = (r * 128 + j * 32 + lane) << 2;
                    if (v[j].w != 0.0f) my = jb + 3;
                    if (v[j].z != 0.0f) my = jb + 2;
                    if (v[j].y != 0.0f) my = jb + 1;
                    if (v[j].x != 0.0f) my = jb;
                }
                const unsigned m = __ballot_sync(0xffffffffu, my >= 0);
                if (m) idx1 = __shfl_sync(0xffffffffu, my, __ffs(m) - 1);
            }
            if (idx0 >= 0 && idx1 >= 0) break;
        }
        if (idx0 < 0) idx0 = 0;
        if (idx1 < 0) idx1 = 0;

        // Wait for GEMM completion (hidden under other warps' streaming).
        if (lane == 0) {
            while (*(volatile int*)&g_done < GEMM_BLOCKS) __nanosleep(100);
        }
        __syncwarp();
        __threadfence();

        const int b0 = a0 >> 14;
        const int b1 = a1 >> 14;
        const float2* __restrict__ src0 = reinterpret_cast<const float2*>(
            g_res_logits + ((size_t)b0 * NRES + idx0) * COUT);
        const float2* __restrict__ src1 = reinterpret_cast<const float2*>(
            g_res_logits + ((size_t)b1 * NRES + idx1) * COUT);
        float2* __restrict__ dst0 = reinterpret_cast<float2*>(out + (size_t)a0 * COUT);
        float2* __restrict__ dst1 = reinterpret_cast<float2*>(out + (size_t)a1 * COUT);

        if (lane < COUT / 2) {
            const float2 x0 = src0[lane];
            const float2 x1 = src1[lane];
            dst0[lane] = x0;
            dst1[lane] = x1;
        }

        // Last scan block resets counters for the next graph replay.
        __syncthreads();
        if (tid == 0) {
            const int old = atomicAdd(&g_scanfin, 1);
            if (old == SCAN_BLOCKS - 1) {
                g_done    = 0;
                g_scanfin = 0;
            }
        }
    }
}

extern "C" void kernel_launch(void* const* d_in, const int* in_sizes, int n_in,
                              void* d_out, int out_size)
{
    const float* s    = (const float*)d_in[0];
    const float* tta  = (const float*)d_in[1];
    const float* W    = (const float*)d_in[2];
    const float* bias = (const float*)d_in[3];
    float* out = (float*)d_out;

    (void)in_sizes; (void)n_in; (void)out_size;

    fused_kernel<<<GEMM_BLOCKS + SCAN_BLOCKS, 256>>>(s, tta, W, bias, out);
}

// round 6
// speedup vs baseline: 1.4273x; 1.3212x over previous
#include <cuda_runtime.h>
#include <cstdint>

#define B_     2
#define NRES   2048
#define NATOM  16384
#define CS     384
#define COUT   50
#define OPAD   64
#define KT     64
#define RPB    32
#define GEMM_BLOCKS ((B_ * NRES) / RPB)   // 128
#define SCAN_BLOCKS ((B_ * NATOM) / 8)    // 4096

// Scratch
__device__ float g_res_logits[B_ * NRES * COUT];   // 3.2 MB

// ---------------------------------------------------------------------------
// Kernel A: res_logits = s @ W^T + b.  Runs alone (~4-5us), so no issue-slot
// contention. 128 blocks, 32 rows each, in-smem W transpose per K-tile.
// ---------------------------------------------------------------------------
__global__ void __launch_bounds__(256)
gemm_kernel(const float* __restrict__ s,     // [B, NRES, CS]
            const float* __restrict__ W,     // [COUT, CS]
            const float* __restrict__ bias)  // [COUT]
{
    __shared__ float s_sm[RPB][KT];     // 8 KB
    __shared__ float wt_sm[KT][OPAD];   // 16 KB

    const int tid = threadIdx.x;
    const int to  = tid & 15;
    const int tr  = tid >> 4;
    const int o0  = to << 2;
    const int r0  = tr << 1;
    const int r1  = r0 + 1;
    const int row0 = blockIdx.x * RPB;

    const int wo = tid & 63;          // out channel for W transpose loads
    const int wg = tid >> 6;          // k-group 0..3

    float4 accA = make_float4(0.f, 0.f, 0.f, 0.f);
    float4 accB = make_float4(0.f, 0.f, 0.f, 0.f);

    for (int kt = 0; kt < CS; kt += KT) {
        {   // s tile: 32 rows x 64 k = 512 float4, coalesced
            const float4* __restrict__ sg = reinterpret_cast<const float4*>(s);
            float4* s4 = reinterpret_cast<float4*>(&s_sm[0][0]);
            #pragma unroll
            for (int i = 0; i < 2; ++i) {
                const int f = tid + 256 * i;
                const int r = f >> 4;
                const int c = f & 15;
                s4[f] = sg[(size_t)(row0 + r) * (CS / 4) + (kt >> 2) + c];
            }
        }
        // W tile transposed in-smem: lanes stride o -> conflict-free STS
        #pragma unroll
        for (int m = 0; m < 4; ++m) {
            const int k0 = (wg << 4) + (m << 2);
            float4 v = make_float4(0.f, 0.f, 0.f, 0.f);
            if (wo < COUT)
                v = *reinterpret_cast<const float4*>(&W[(size_t)wo * CS + kt + k0]);
            wt_sm[k0 + 0][wo] = v.x;
            wt_sm[k0 + 1][wo] = v.y;
            wt_sm[k0 + 2][wo] = v.z;
            wt_sm[k0 + 3][wo] = v.w;
        }
        __syncthreads();

        #pragma unroll
        for (int kk = 0; kk < KT; kk += 4) {
            const float4 sa = *reinterpret_cast<const float4*>(&s_sm[r0][kk]);
            const float4 sb = *reinterpret_cast<const float4*>(&s_sm[r1][kk]);
            const float4 w0 = *reinterpret_cast<const float4*>(&wt_sm[kk + 0][o0]);
            const float4 w1 = *reinterpret_cast<const float4*>(&wt_sm[kk + 1][o0]);
            const float4 w2 = *reinterpret_cast<const float4*>(&wt_sm[kk + 2][o0]);
            const float4 w3 = *reinterpret_cast<const float4*>(&wt_sm[kk + 3][o0]);

            accA.x = fmaf(sa.x, w0.x, accA.x); accA.y = fmaf(sa.x, w0.y, accA.y);
            accA.z = fmaf(sa.x, w0.z, accA.z); accA.w = fmaf(sa.x, w0.w, accA.w);
            accB.x = fmaf(sb.x, w0.x, accB.x); accB.y = fmaf(sb.x, w0.y, accB.y);
            accB.z = fmaf(sb.x, w0.z, accB.z); accB.w = fmaf(sb.x, w0.w, accB.w);

            accA.x = fmaf(sa.y, w1.x, accA.x); accA.y = fmaf(sa.y, w1.y, accA.y);
            accA.z = fmaf(sa.y, w1.z, accA.z); accA.w = fmaf(sa.y, w1.w, accA.w);
            accB.x = fmaf(sb.y, w1.x, accB.x); accB.y = fmaf(sb.y, w1.y, accB.y);
            accB.z = fmaf(sb.y, w1.z, accB.z); accB.w = fmaf(sb.y, w1.w, accB.w);

            accA.x = fmaf(sa.z, w2.x, accA.x); accA.y = fmaf(sa.z, w2.y, accA.y);
            accA.z = fmaf(sa.z, w2.z, accA.z); accA.w = fmaf(sa.z, w2.w, accA.w);
            accB.x = fmaf(sb.z, w2.x, accB.x); accB.y = fmaf(sb.z, w2.y, accB.y);
            accB.z = fmaf(sb.z, w2.z, accB.z); accB.w = fmaf(sb.z, w2.w, accB.w);

            accA.x = fmaf(sa.w, w3.x, accA.x); accA.y = fmaf(sa.w, w3.y, accA.y);
            accA.z = fmaf(sa.w, w3.z, accA.z); accA.w = fmaf(sa.w, w3.w, accA.w);
            accB.x = fmaf(sb.w, w3.x, accB.x); accB.y = fmaf(sb.w, w3.y, accB.y);
            accB.z = fmaf(sb.w, w3.z, accB.z); accB.w = fmaf(sb.w, w3.w, accB.w);
        }
        __syncthreads();
    }

    const float aA[4] = {accA.x, accA.y, accA.z, accA.w};
    const float aB[4] = {accB.x, accB.y, accB.z, accB.w};
    #pragma unroll
    for (int c = 0; c < 4; ++c) {
        const int o = o0 + c;
        if (o < COUT) {
            const float bv = bias[o];
            g_res_logits[(size_t)(row0 + r0) * COUT + o] = aA[c] + bv;
            g_res_logits[(size_t)(row0 + r1) * COUT + o] = aB[c] + bv;
        }
    }
}

// ---------------------------------------------------------------------------
// Kernel B: warp per atom. Scan one-hot row (512-float rounds, 4x LDG.128
// in flight), ballot early-exit, then gather 50 floats directly to out.
// res_logits is complete (separate launch) -> no sync needed.
// ---------------------------------------------------------------------------
__global__ void __launch_bounds__(256)
scan_gather_kernel(const float* __restrict__ tta,   // [B, NATOM, NRES]
                   float* __restrict__ out)         // [B, NATOM, COUT]
{
    const int gwarp = (blockIdx.x * blockDim.x + threadIdx.x) >> 5;
    const int lane  = threadIdx.x & 31;

    const float4* __restrict__ row =
        reinterpret_cast<const float4*>(tta + (size_t)gwarp * NRES);

    int idx = 0;
    // 512 float4 per row; rounds of 128 float4 (512 floats), MLP=4 LDG.128
    #pragma unroll 1
    for (int r = 0; r < 4; ++r) {
        float4 v[4];
        #pragma unroll
        for (int j = 0; j < 4; ++j)
            v[j] = __ldcs(&row[r * 128 + j * 32 + lane]);

        int my = -1;
        #pragma unroll
        for (int j = 3; j >= 0; --j) {
            const int jb = (r * 128 + j * 32 + lane) << 2;
            if (v[j].w != 0.0f) my = jb + 3;
            if (v[j].z != 0.0f) my = jb + 2;
            if (v[j].y != 0.0f) my = jb + 1;
            if (v[j].x != 0.0f) my = jb;
        }

        const unsigned m = __ballot_sync(0xffffffffu, my >= 0);
        if (m) {
            idx = __shfl_sync(0xffffffffu, my, __ffs(m) - 1);
            break;
        }
    }

    // Immediate gather: 25 lanes x float2 = 200 B (res_logits is L2-resident).
    const int b = gwarp >> 14;
    const float2* __restrict__ src = reinterpret_cast<const float2*>(
        g_res_logits + ((size_t)b * NRES + idx) * COUT);
    float2* __restrict__ dst = reinterpret_cast<float2*>(
        out + (size_t)gwarp * COUT);
    if (lane < COUT / 2) dst[lane] = src[lane];
}

extern "C" void kernel_launch(void* const* d_in, const int* in_sizes, int n_in,
                              void* d_out, int out_size)
{
    const float* s    = (const float*)d_in[0];  // [B, NRES, CS]
    const float* tta  = (const float*)d_in[1];  // [B, NATOM, NRES]
    const float* W    = (const float*)d_in[2];  // [COUT, CS]
    const float* bias = (const float*)d_in[3];  // [COUT]
    float* out = (float*)d_out;

    (void)in_sizes; (void)n_in; (void)out_size;

    gemm_kernel<<<GEMM_BLOCKS, 256>>>(s, W, bias);
    scan_gather_kernel<<<SCAN_BLOCKS, 256>>>(tta, out);
}

// round 7
// speedup vs baseline: 1.6379x; 1.1476x over previous
#include <cuda_runtime.h>
#include <cstdint>

#define B_     2
#define NRES   2048
#define NATOM  16384
#define CS     384
#define COUT   50
#define OPAD   64
#define KT     64
#define RPB    32
#define GEMM_BLOCKS ((B_ * NRES) / RPB)    // 128
#define SCAN_BLOCKS ((B_ * NATOM) / 16)    // 2048 (2 atoms/warp, 8 warps/block)

// Scratch
__device__ float g_res_logits[B_ * NRES * COUT];   // 3.2 MB
__device__ int   g_idx[B_ * NATOM];                // 128 KB

// ---------------------------------------------------------------------------
// Fused kernel (NO inter-block dependency):
//   blocks [0, 128):    GEMM res_logits = s @ W^T + b  (hidden under scan)
//   blocks [128, 2176): warp scans TWO one-hot rows (MLP=8 LDG.128),
//                       ballot early-exit per row, writes g_idx.
// ---------------------------------------------------------------------------
__global__ void __launch_bounds__(256)
fused_kernel(const float* __restrict__ s,     // [B, NRES, CS]
             const float* __restrict__ tta,   // [B, NATOM, NRES]
             const float* __restrict__ W,     // [COUT, CS]
             const float* __restrict__ bias)  // [COUT]
{
    __shared__ float s_sm[RPB][KT];     // 8 KB
    __shared__ float wt_sm[KT][OPAD];   // 16 KB

    const int tid = threadIdx.x;

    if (blockIdx.x < GEMM_BLOCKS) {
        // ----------------- GEMM branch -----------------
        const int to  = tid & 15;
        const int tr  = tid >> 4;
        const int o0  = to << 2;
        const int r0  = tr << 1;
        const int r1  = r0 + 1;
        const int row0 = blockIdx.x * RPB;

        const int wo = tid & 63;
        const int wg = tid >> 6;

        float4 accA = make_float4(0.f, 0.f, 0.f, 0.f);
        float4 accB = make_float4(0.f, 0.f, 0.f, 0.f);

        for (int kt = 0; kt < CS; kt += KT) {
            {
                const float4* __restrict__ sg = reinterpret_cast<const float4*>(s);
                float4* s4 = reinterpret_cast<float4*>(&s_sm[0][0]);
                #pragma unroll
                for (int i = 0; i < 2; ++i) {
                    const int f = tid + 256 * i;
                    const int r = f >> 4;
                    const int c = f & 15;
                    s4[f] = sg[(size_t)(row0 + r) * (CS / 4) + (kt >> 2) + c];
                }
            }
            #pragma unroll
            for (int m = 0; m < 4; ++m) {
                const int k0 = (wg << 4) + (m << 2);
                float4 v = make_float4(0.f, 0.f, 0.f, 0.f);
                if (wo < COUT)
                    v = *reinterpret_cast<const float4*>(&W[(size_t)wo * CS + kt + k0]);
                wt_sm[k0 + 0][wo] = v.x;
                wt_sm[k0 + 1][wo] = v.y;
                wt_sm[k0 + 2][wo] = v.z;
                wt_sm[k0 + 3][wo] = v.w;
            }
            __syncthreads();

            #pragma unroll
            for (int kk = 0; kk < KT; kk += 4) {
                const float4 sa = *reinterpret_cast<const float4*>(&s_sm[r0][kk]);
                const float4 sb = *reinterpret_cast<const float4*>(&s_sm[r1][kk]);
                const float4 w0 = *reinterpret_cast<const float4*>(&wt_sm[kk + 0][o0]);
                const float4 w1 = *reinterpret_cast<const float4*>(&wt_sm[kk + 1][o0]);
                const float4 w2 = *reinterpret_cast<const float4*>(&wt_sm[kk + 2][o0]);
                const float4 w3 = *reinterpret_cast<const float4*>(&wt_sm[kk + 3][o0]);

                accA.x = fmaf(sa.x, w0.x, accA.x); accA.y = fmaf(sa.x, w0.y, accA.y);
                accA.z = fmaf(sa.x, w0.z, accA.z); accA.w = fmaf(sa.x, w0.w, accA.w);
                accB.x = fmaf(sb.x, w0.x, accB.x); accB.y = fmaf(sb.x, w0.y, accB.y);
                accB.z = fmaf(sb.x, w0.z, accB.z); accB.w = fmaf(sb.x, w0.w, accB.w);

                accA.x = fmaf(sa.y, w1.x, accA.x); accA.y = fmaf(sa.y, w1.y, accA.y);
                accA.z = fmaf(sa.y, w1.z, accA.z); accA.w = fmaf(sa.y, w1.w, accA.w);
                accB.x = fmaf(sb.y, w1.x, accB.x); accB.y = fmaf(sb.y, w1.y, accB.y);
                accB.z = fmaf(sb.y, w1.z, accB.z); accB.w = fmaf(sb.y, w1.w, accB.w);

                accA.x = fmaf(sa.z, w2.x, accA.x); accA.y = fmaf(sa.z, w2.y, accA.y);
                accA.z = fmaf(sa.z, w2.z, accA.z); accA.w = fmaf(sa.z, w2.w, accA.w);
                accB.x = fmaf(sb.z, w2.x, accB.x); accB.y = fmaf(sb.z, w2.y, accB.y);
                accB.z = fmaf(sb.z, w2.z, accB.z); accB.w = fmaf(sb.z, w2.w, accB.w);

                accA.x = fmaf(sa.w, w3.x, accA.x); accA.y = fmaf(sa.w, w3.y, accA.y);
                accA.z = fmaf(sa.w, w3.z, accA.z); accA.w = fmaf(sa.w, w3.w, accA.w);
                accB.x = fmaf(sb.w, w3.x, accB.x); accB.y = fmaf(sb.w, w3.y, accB.y);
                accB.z = fmaf(sb.w, w3.z, accB.z); accB.w = fmaf(sb.w, w3.w, accB.w);
            }
            __syncthreads();
        }

        const float aA[4] = {accA.x, accA.y, accA.z, accA.w};
        const float aB[4] = {accB.x, accB.y, accB.z, accB.w};
        #pragma unroll
        for (int c = 0; c < 4; ++c) {
            const int o = o0 + c;
            if (o < COUT) {
                const float bv = bias[o];
                g_res_logits[(size_t)(row0 + r0) * COUT + o] = aA[c] + bv;
                g_res_logits[(size_t)(row0 + r1) * COUT + o] = aB[c] + bv;
            }
        }
    } else {
        // -------- scan branch: 2 atoms per warp, MLP = 8 x LDG.128 --------
        const int gw   = (blockIdx.x - GEMM_BLOCKS) * 8 + (tid >> 5);
        const int lane = tid & 31;
        const int a0   = gw * 2;
        const int a1   = a0 + 1;

        const float4* __restrict__ rowA =
            reinterpret_cast<const float4*>(tta + (size_t)a0 * NRES);
        const float4* __restrict__ rowB =
            reinterpret_cast<const float4*>(tta + (size_t)a1 * NRES);

        int idx0 = -1, idx1 = -1;

        #pragma unroll 1
        for (int r = 0; r < 4; ++r) {
            const bool need0 = (idx0 < 0);   // warp-uniform
            const bool need1 = (idx1 < 0);

            float4 u[4], v[4];
            if (need0) {
                #pragma unroll
                for (int j = 0; j < 4; ++j)
                    u[j] = __ldcs(&rowA[r * 128 + j * 32 + lane]);
            }
            if (need1) {
                #pragma unroll
                for (int j = 0; j < 4; ++j)
                    v[j] = __ldcs(&rowB[r * 128 + j * 32 + lane]);
            }

            if (need0) {
                int my = -1;
                #pragma unroll
                for (int j = 3; j >= 0; --j) {
                    const int jb = (r * 128 + j * 32 + lane) << 2;
                    if (u[j].w != 0.0f) my = jb + 3;
                    if (u[j].z != 0.0f) my = jb + 2;
                    if (u[j].y != 0.0f) my = jb + 1;
                    if (u[j].x != 0.0f) my = jb;
                }
                const unsigned m = __ballot_sync(0xffffffffu, my >= 0);
                if (m) idx0 = __shfl_sync(0xffffffffu, my, __ffs(m) - 1);
            }
            if (need1) {
                int my = -1;
                #pragma unroll
                for (int j = 3; j >= 0; --j) {
                    const int jb = (r * 128 + j * 32 + lane) << 2;
                    if (v[j].w != 0.0f) my = jb + 3;
                    if (v[j].z != 0.0f) my = jb + 2;
                    if (v[j].y != 0.0f) my = jb + 1;
                    if (v[j].x != 0.0f) my = jb;
                }
                const unsigned m = __ballot_sync(0xffffffffu, my >= 0);
                if (m) idx1 = __shfl_sync(0xffffffffu, my, __ffs(m) - 1);
            }
            if (idx0 >= 0 && idx1 >= 0) break;
        }
        if (idx0 < 0) idx0 = 0;
        if (idx1 < 0) idx1 = 0;

        if (lane == 0) {
            g_idx[a0] = idx0;
            g_idx[a1] = idx1;
        }
    }
}

// ---------------------------------------------------------------------------
// Gather: 4 atoms per warp, software-pipelined.
//   round 1: lanes 0-3 load the 4 idx (one LDG round), shfl-broadcast
//   round 2: 4 independent 200 B row reads (MLP 4 over L2)
//   round 3: 4 stores
// ---------------------------------------------------------------------------
__global__ void __launch_bounds__(256)
gather_kernel(float* __restrict__ out)
{
    const int gw   = (blockIdx.x * blockDim.x + threadIdx.x) >> 5;
    const int lane = threadIdx.x & 31;
    const int a0   = gw * 4;                 // 4 consecutive atoms

    // one parallel idx load round
    int myv = 0;
    if (lane < 4) myv = g_idx[a0 + lane];
    const int i0 = __shfl_sync(0xffffffffu, myv, 0);
    const int i1 = __shfl_sync(0xffffffffu, myv, 1);
    const int i2 = __shfl_sync(0xffffffffu, myv, 2);
    const int i3 = __shfl_sync(0xffffffffu, myv, 3);

    const int b0 = (a0 + 0) >> 14;
    const int b1 = (a0 + 1) >> 14;
    const int b2 = (a0 + 2) >> 14;
    const int b3 = (a0 + 3) >> 14;

    const float2* __restrict__ s0 = reinterpret_cast<const float2*>(
        g_res_logits + ((size_t)b0 * NRES + i0) * COUT);
    const float2* __restrict__ s1 = reinterpret_cast<const float2*>(
        g_res_logits + ((size_t)b1 * NRES + i1) * COUT);
    const float2* __restrict__ s2 = reinterpret_cast<const float2*>(
        g_res_logits + ((size_t)b2 * NRES + i2) * COUT);
    const float2* __restrict__ s3 = reinterpret_cast<const float2*>(
        g_res_logits + ((size_t)b3 * NRES + i3) * COUT);

    if (lane < COUT / 2) {
        // 4 independent loads issued back-to-back, then 4 stores
        const float2 x0 = s0[lane];
        const float2 x1 = s1[lane];
        const float2 x2 = s2[lane];
        const float2 x3 = s3[lane];
        float2* __restrict__ d = reinterpret_cast<float2*>(out + (size_t)a0 * COUT);
        d[lane]               = x0;   // atom a0
        d[lane + 25]          = x1;   // atom a0+1 (COUT/2 = 25 float2 per atom)
        d[lane + 50]          = x2;
        d[lane + 75]          = x3;
    }
}

extern "C" void kernel_launch(void* const* d_in, const int* in_sizes, int n_in,
                              void* d_out, int out_size)
{
    const float* s    = (const float*)d_in[0];  // [B, NRES, CS]
    const float* tta  = (const float*)d_in[1];  // [B, NATOM, NRES]
    const float* W    = (const float*)d_in[2];  // [COUT, CS]
    const float* bias = (const float*)d_in[3];  // [COUT]
    float* out = (float*)d_out;

    (void)in_sizes; (void)n_in; (void)out_size;

    fused_kernel<<<GEMM_BLOCKS + SCAN_BLOCKS, 256>>>(s, tta, W, bias);
    // 32768 atoms / 4 per warp = 8192 warps / 8 warps per block = 1024 blocks
    gather_kernel<<<1024, 256>>>(out);
}

// round 8
// speedup vs baseline: 1.6392x; 1.0008x over previous
#include <cuda_runtime.h>
#include <cstdint>

#define B_     2
#define NRES   2048
#define NATOM  16384
#define CS     384
#define COUT   50
#define OPAD   64
#define KT     64
#define RPB    32
#define GEMM_BLOCKS   ((B_ * NRES) / RPB)    // 128
#define SCAN_BLOCKS   ((B_ * NATOM) / 8)     // 4096 (1 atom/warp, 8 warps/block)
#define GATHER_BLOCKS ((B_ * NATOM) / 32)    // 1024 (4 atoms/warp, 8 warps/block)
#define SCAN_BASE     GEMM_BLOCKS
#define GATHER_BASE   (GEMM_BLOCKS + SCAN_BLOCKS)

// Scratch + counters (restored to 0 at exit -> graph-replay safe)
__device__ float g_res_logits[B_ * NRES * COUT];   // 3.2 MB
__device__ int   g_idx[B_ * NATOM];                // 128 KB
__device__ int   g_done      = 0;                  // GEMM blocks finished
__device__ int   g_scanfin   = 0;                  // scan blocks finished
__device__ int   g_gatherfin = 0;                  // gather blocks finished

// ---------------------------------------------------------------------------
// One kernel, three roles by blockIdx (dispatch order = low bids first):
//   [0,128):        GEMM  (never waits)
//   [128,4224):     scan  (never waits)  - 1 atom/warp, MLP=4 LDG.128
//   [4224,5248):    gather (dispatched in the LAST wave; producers are done
//                   or nearly done by then, so the spin is ~free)
// ---------------------------------------------------------------------------
__global__ void __launch_bounds__(256)
fused_kernel(const float* __restrict__ s,     // [B, NRES, CS]
             const float* __restrict__ tta,   // [B, NATOM, NRES]
             const float* __restrict__ W,     // [COUT, CS]
             const float* __restrict__ bias,  // [COUT]
             float* __restrict__ out)         // [B, NATOM, COUT]
{
    __shared__ float s_sm[RPB][KT];     // 8 KB
    __shared__ float wt_sm[KT][OPAD];   // 16 KB

    const int tid = threadIdx.x;

    if (blockIdx.x < GEMM_BLOCKS) {
        // ----------------- GEMM branch -----------------
        const int to  = tid & 15;
        const int tr  = tid >> 4;
        const int o0  = to << 2;
        const int r0  = tr << 1;
        const int r1  = r0 + 1;
        const int row0 = blockIdx.x * RPB;

        const int wo = tid & 63;
        const int wg = tid >> 6;

        float4 accA = make_float4(0.f, 0.f, 0.f, 0.f);
        float4 accB = make_float4(0.f, 0.f, 0.f, 0.f);

        for (int kt = 0; kt < CS; kt += KT) {
            {
                const float4* __restrict__ sg = reinterpret_cast<const float4*>(s);
                float4* s4 = reinterpret_cast<float4*>(&s_sm[0][0]);
                #pragma unroll
                for (int i = 0; i < 2; ++i) {
                    const int f = tid + 256 * i;
                    const int r = f >> 4;
                    const int c = f & 15;
                    s4[f] = sg[(size_t)(row0 + r) * (CS / 4) + (kt >> 2) + c];
                }
            }
            #pragma unroll
            for (int m = 0; m < 4; ++m) {
                const int k0 = (wg << 4) + (m << 2);
                float4 v = make_float4(0.f, 0.f, 0.f, 0.f);
                if (wo < COUT)
                    v = *reinterpret_cast<const float4*>(&W[(size_t)wo * CS + kt + k0]);
                wt_sm[k0 + 0][wo] = v.x;
                wt_sm[k0 + 1][wo] = v.y;
                wt_sm[k0 + 2][wo] = v.z;
                wt_sm[k0 + 3][wo] = v.w;
            }
            __syncthreads();

            #pragma unroll
            for (int kk = 0; kk < KT; kk += 4) {
                const float4 sa = *reinterpret_cast<const float4*>(&s_sm[r0][kk]);
                const float4 sb = *reinterpret_cast<const float4*>(&s_sm[r1][kk]);
                const float4 w0 = *reinterpret_cast<const float4*>(&wt_sm[kk + 0][o0]);
                const float4 w1 = *reinterpret_cast<const float4*>(&wt_sm[kk + 1][o0]);
                const float4 w2 = *reinterpret_cast<const float4*>(&wt_sm[kk + 2][o0]);
                const float4 w3 = *reinterpret_cast<const float4*>(&wt_sm[kk + 3][o0]);

                accA.x = fmaf(sa.x, w0.x, accA.x); accA.y = fmaf(sa.x, w0.y, accA.y);
                accA.z = fmaf(sa.x, w0.z, accA.z); accA.w = fmaf(sa.x, w0.w, accA.w);
                accB.x = fmaf(sb.x, w0.x, accB.x); accB.y = fmaf(sb.x, w0.y, accB.y);
                accB.z = fmaf(sb.x, w0.z, accB.z); accB.w = fmaf(sb.x, w0.w, accB.w);

                accA.x = fmaf(sa.y, w1.x, accA.x); accA.y = fmaf(sa.y, w1.y, accA.y);
                accA.z = fmaf(sa.y, w1.z, accA.z); accA.w = fmaf(sa.y, w1.w, accA.w);
                accB.x = fmaf(sb.y, w1.x, accB.x); accB.y = fmaf(sb.y, w1.y, accB.y);
                accB.z = fmaf(sb.y, w1.z, accB.z); accB.w = fmaf(sb.y, w1.w, accB.w);

                accA.x = fmaf(sa.z, w2.x, accA.x); accA.y = fmaf(sa.z, w2.y, accA.y);
                accA.z = fmaf(sa.z, w2.z, accA.z); accA.w = fmaf(sa.z, w2.w, accA.w);
                accB.x = fmaf(sb.z, w2.x, accB.x); accB.y = fmaf(sb.z, w2.y, accB.y);
                accB.z = fmaf(sb.z, w2.z, accB.z); accB.w = fmaf(sb.z, w2.w, accB.w);

                accA.x = fmaf(sa.w, w3.x, accA.x); accA.y = fmaf(sa.w, w3.y, accA.y);
                accA.z = fmaf(sa.w, w3.z, accA.z); accA.w = fmaf(sa.w, w3.w, accA.w);
                accB.x = fmaf(sb.w, w3.x, accB.x); accB.y = fmaf(sb.w, w3.y, accB.y);
                accB.z = fmaf(sb.w, w3.z, accB.z); accB.w = fmaf(sb.w, w3.w, accB.w);
            }
            __syncthreads();
        }

        const float aA[4] = {accA.x, accA.y, accA.z, accA.w};
        const float aB[4] = {accB.x, accB.y, accB.z, accB.w};
        #pragma unroll
        for (int c = 0; c < 4; ++c) {
            const int o = o0 + c;
            if (o < COUT) {
                const float bv = bias[o];
                g_res_logits[(size_t)(row0 + r0) * COUT + o] = aA[c] + bv;
                g_res_logits[(size_t)(row0 + r1) * COUT + o] = aB[c] + bv;
            }
        }

        __threadfence();          // each thread publishes its own stores
        __syncthreads();
        if (tid == 0) atomicAdd(&g_done, 1);

    } else if (blockIdx.x < GATHER_BASE) {
        // -------- scan branch: 1 atom/warp, rounds of 512 floats (MLP=4) ----
        const int gwarp = (blockIdx.x - SCAN_BASE) * 8 + (tid >> 5);
        const int lane  = tid & 31;

        const float4* __restrict__ row =
            reinterpret_cast<const float4*>(tta + (size_t)gwarp * NRES);

        int idx = 0;
        #pragma unroll 1
        for (int r = 0; r < 4; ++r) {
            float4 v[4];
            #pragma unroll
            for (int j = 0; j < 4; ++j)
                v[j] = __ldcs(&row[r * 128 + j * 32 + lane]);

            int my = -1;
            #pragma unroll
            for (int j = 3; j >= 0; --j) {
                const int jb = (r * 128 + j * 32 + lane) << 2;
                if (v[j].w != 0.0f) my = jb + 3;
                if (v[j].z != 0.0f) my = jb + 2;
                if (v[j].y != 0.0f) my = jb + 1;
                if (v[j].x != 0.0f) my = jb;
            }

            const unsigned m = __ballot_sync(0xffffffffu, my >= 0);
            if (m) {
                idx = __shfl_sync(0xffffffffu, my, __ffs(m) - 1);
                break;
            }
        }

        if (lane == 0) {
            g_idx[gwarp] = idx;
            __threadfence();      // publish before this block is counted
        }
        __syncthreads();
        if (tid == 0) atomicAdd(&g_scanfin, 1);

    } else {
        // -------- gather branch (last-dispatched wave): 4 atoms/warp --------
        if (tid == 0) {
            while (*(volatile int*)&g_done < GEMM_BLOCKS ||
                   *(volatile int*)&g_scanfin < SCAN_BLOCKS)
                __nanosleep(128);
        }
        __syncthreads();
        __threadfence();          // acquire: order reads after flag observation

        const int gw   = (blockIdx.x - GATHER_BASE) * 8 + (tid >> 5);
        const int lane = tid & 31;
        const int a0   = gw * 4;

        int myv = 0;
        if (lane < 4) myv = g_idx[a0 + lane];
        const int i0 = __shfl_sync(0xffffffffu, myv, 0);
        const int i1 = __shfl_sync(0xffffffffu, myv, 1);
        const int i2 = __shfl_sync(0xffffffffu, myv, 2);
        const int i3 = __shfl_sync(0xffffffffu, myv, 3);

        const int b0 = (a0 + 0) >> 14;
        const int b1 = (a0 + 1) >> 14;
        const int b2 = (a0 + 2) >> 14;
        const int b3 = (a0 + 3) >> 14;

        const float2* __restrict__ s0 = reinterpret_cast<const float2*>(
            g_res_logits + ((size_t)b0 * NRES + i0) * COUT);
        const float2* __restrict__ s1 = reinterpret_cast<const float2*>(
            g_res_logits + ((size_t)b1 * NRES + i1) * COUT);
        const float2* __restrict__ s2 = reinterpret_cast<const float2*>(
            g_res_logits + ((size_t)b2 * NRES + i2) * COUT);
        const float2* __restrict__ s3 = reinterpret_cast<const float2*>(
            g_res_logits + ((size_t)b3 * NRES + i3) * COUT);

        if (lane < COUT / 2) {
            const float2 x0 = s0[lane];
            const float2 x1 = s1[lane];
            const float2 x2 = s2[lane];
            const float2 x3 = s3[lane];
            float2* __restrict__ d =
                reinterpret_cast<float2*>(out + (size_t)a0 * COUT);
            d[lane]      = x0;
            d[lane + 25] = x1;     // COUT/2 = 25 float2 per atom
            d[lane + 50] = x2;
            d[lane + 75] = x3;
        }

        // Last gather block resets counters for the next graph replay.
        __syncthreads();
        if (tid == 0) {
            const int old = atomicAdd(&g_gatherfin, 1);
            if (old == GATHER_BLOCKS - 1) {
                g_done      = 0;
                g_scanfin   = 0;
                g_gatherfin = 0;
            }
        }
    }
}

extern "C" void kernel_launch(void* const* d_in, const int* in_sizes, int n_in,
                              void* d_out, int out_size)
{
    const float* s    = (const float*)d_in[0];  // [B, NRES, CS]
    const float* tta  = (const float*)d_in[1];  // [B, NATOM, NRES]
    const float* W    = (const float*)d_in[2];  // [COUT, CS]
    const float* bias = (const float*)d_in[3];  // [COUT]
    float* out = (float*)d_out;

    (void)in_sizes; (void)n_in; (void)out_size;

    fused_kernel<<<GEMM_BLOCKS + SCAN_BLOCKS + GATHER_BLOCKS, 256>>>(
        s, tta, W, bias, out);
}

// round 9
// speedup vs baseline: 1.7989x; 1.0974x over previous
#include <cuda_runtime.h>
#include <cstdint>

#define B_     2
#define NRES   2048
#define NATOM  16384
#define CS     384
#define COUT   50
#define OPAD   64
#define KT     64
#define RPB    32
#define GEMM_BLOCKS ((B_ * NRES) / RPB)   // 128
#define SCAN_BLOCKS ((B_ * NATOM) / 8)    // 4096 (1 atom/warp, 8 warps/block)

// Scratch
__device__ float g_res_logits[B_ * NRES * COUT];   // 3.2 MB
__device__ int   g_idx[B_ * NATOM];                // 128 KB

// ---------------------------------------------------------------------------
// Fused kernel (R3 structure, NO inter-block sync):
//   blocks [0, 128):    GEMM res_logits = s @ W^T + b  (hidden under scan)
//   blocks [128, 4224): warp-per-atom one-hot scan, 512-float rounds
//                       (MLP = 4x LDG.128), ballot early-exit -> g_idx
// ---------------------------------------------------------------------------
__global__ void __launch_bounds__(256)
fused_kernel(const float* __restrict__ s,     // [B, NRES, CS]
             const float* __restrict__ tta,   // [B, NATOM, NRES]
             const float* __restrict__ W,     // [COUT, CS]
             const float* __restrict__ bias)  // [COUT]
{
    __shared__ float s_sm[RPB][KT];     // 8 KB
    __shared__ float wt_sm[KT][OPAD];   // 16 KB

    const int tid = threadIdx.x;

    if (blockIdx.x < GEMM_BLOCKS) {
        // ----------------- GEMM branch -----------------
        const int to  = tid & 15;
        const int tr  = tid >> 4;
        const int o0  = to << 2;
        const int r0  = tr << 1;
        const int r1  = r0 + 1;
        const int row0 = blockIdx.x * RPB;

        const int wo = tid & 63;
        const int wg = tid >> 6;

        float4 accA = make_float4(0.f, 0.f, 0.f, 0.f);
        float4 accB = make_float4(0.f, 0.f, 0.f, 0.f);

        for (int kt = 0; kt < CS; kt += KT) {
            {
                const float4* __restrict__ sg = reinterpret_cast<const float4*>(s);
                float4* s4 = reinterpret_cast<float4*>(&s_sm[0][0]);
                #pragma unroll
                for (int i = 0; i < 2; ++i) {
                    const int f = tid + 256 * i;
                    const int r = f >> 4;
                    const int c = f & 15;
                    s4[f] = sg[(size_t)(row0 + r) * (CS / 4) + (kt >> 2) + c];
                }
            }
            #pragma unroll
            for (int m = 0; m < 4; ++m) {
                const int k0 = (wg << 4) + (m << 2);
                float4 v = make_float4(0.f, 0.f, 0.f, 0.f);
                if (wo < COUT)
                    v = *reinterpret_cast<const float4*>(&W[(size_t)wo * CS + kt + k0]);
                wt_sm[k0 + 0][wo] = v.x;
                wt_sm[k0 + 1][wo] = v.y;
                wt_sm[k0 + 2][wo] = v.z;
                wt_sm[k0 + 3][wo] = v.w;
            }
            __syncthreads();

            #pragma unroll
            for (int kk = 0; kk < KT; kk += 4) {
                const float4 sa = *reinterpret_cast<const float4*>(&s_sm[r0][kk]);
                const float4 sb = *reinterpret_cast<const float4*>(&s_sm[r1][kk]);
                const float4 w0 = *reinterpret_cast<const float4*>(&wt_sm[kk + 0][o0]);
                const float4 w1 = *reinterpret_cast<const float4*>(&wt_sm[kk + 1][o0]);
                const float4 w2 = *reinterpret_cast<const float4*>(&wt_sm[kk + 2][o0]);
                const float4 w3 = *reinterpret_cast<const float4*>(&wt_sm[kk + 3][o0]);

                accA.x = fmaf(sa.x, w0.x, accA.x); accA.y = fmaf(sa.x, w0.y, accA.y);
                accA.z = fmaf(sa.x, w0.z, accA.z); accA.w = fmaf(sa.x, w0.w, accA.w);
                accB.x = fmaf(sb.x, w0.x, accB.x); accB.y = fmaf(sb.x, w0.y, accB.y);
                accB.z = fmaf(sb.x, w0.z, accB.z); accB.w = fmaf(sb.x, w0.w, accB.w);

                accA.x = fmaf(sa.y, w1.x, accA.x); accA.y = fmaf(sa.y, w1.y, accA.y);
                accA.z = fmaf(sa.y, w1.z, accA.z); accA.w = fmaf(sa.y, w1.w, accA.w);
                accB.x = fmaf(sb.y, w1.x, accB.x); accB.y = fmaf(sb.y, w1.y, accB.y);
                accB.z = fmaf(sb.y, w1.z, accB.z); accB.w = fmaf(sb.y, w1.w, accB.w);

                accA.x = fmaf(sa.z, w2.x, accA.x); accA.y = fmaf(sa.z, w2.y, accA.y);
                accA.z = fmaf(sa.z, w2.z, accA.z); accA.w = fmaf(sa.z, w2.w, accA.w);
                accB.x = fmaf(sb.z, w2.x, accB.x); accB.y = fmaf(sb.z, w2.y, accB.y);
                accB.z = fmaf(sb.z, w2.z, accB.z); accB.w = fmaf(sb.z, w2.w, accB.w);

                accA.x = fmaf(sa.w, w3.x, accA.x); accA.y = fmaf(sa.w, w3.y, accA.y);
                accA.z = fmaf(sa.w, w3.z, accA.z); accA.w = fmaf(sa.w, w3.w, accA.w);
                accB.x = fmaf(sb.w, w3.x, accB.x); accB.y = fmaf(sb.w, w3.y, accB.y);
                accB.z = fmaf(sb.w, w3.z, accB.z); accB.w = fmaf(sb.w, w3.w, accB.w);
            }
            __syncthreads();
        }

        const float aA[4] = {accA.x, accA.y, accA.z, accA.w};
        const float aB[4] = {accB.x, accB.y, accB.z, accB.w};
        #pragma unroll
        for (int c = 0; c < 4; ++c) {
            const int o = o0 + c;
            if (o < COUT) {
                const float bv = bias[o];
                g_res_logits[(size_t)(row0 + r0) * COUT + o] = aA[c] + bv;
                g_res_logits[(size_t)(row0 + r1) * COUT + o] = aB[c] + bv;
            }
        }
    } else {
        // -------- scan branch: 1 atom/warp, 512-float rounds, MLP=4 --------
        const int gwarp = (blockIdx.x - GEMM_BLOCKS) * 8 + (tid >> 5);
        const int lane  = tid & 31;

        const float4* __restrict__ row =
            reinterpret_cast<const float4*>(tta + (size_t)gwarp * NRES);

        int idx = 0;
        #pragma unroll 1
        for (int r = 0; r < 4; ++r) {
            float4 v[4];
            #pragma unroll
            for (int j = 0; j < 4; ++j)
                v[j] = __ldcs(&row[r * 128 + j * 32 + lane]);

            int my = -1;
            #pragma unroll
            for (int j = 3; j >= 0; --j) {
                const int jb = (r * 128 + j * 32 + lane) << 2;
                if (v[j].w != 0.0f) my = jb + 3;
                if (v[j].z != 0.0f) my = jb + 2;
                if (v[j].y != 0.0f) my = jb + 1;
                if (v[j].x != 0.0f) my = jb;
            }

            const unsigned m = __ballot_sync(0xffffffffu, my >= 0);
            if (m) {
                idx = __shfl_sync(0xffffffffu, my, __ffs(m) - 1);
                break;
            }
        }

        if (lane == 0) g_idx[gwarp] = idx;
    }
}

// ---------------------------------------------------------------------------
// Gather: 8 atoms per warp.
//   round 1: lanes 0-7 load the 8 idx in one parallel LDG round, shfl
//   round 2: 8 independent 200 B row reads (MLP 8, all L2-resident)
//   round 3: 8 coalesced stores
// a0 is a multiple of 8 and NATOM is a multiple of 8 -> all 8 atoms share b.
// ---------------------------------------------------------------------------
__global__ void __launch_bounds__(256)
gather_kernel(float* __restrict__ out)
{
    const int gw   = (blockIdx.x * blockDim.x + threadIdx.x) >> 5;
    const int lane = threadIdx.x & 31;
    const int a0   = gw * 8;                 // 8 consecutive atoms

    int myv = 0;
    if (lane < 8) myv = g_idx[a0 + lane];

    const int b = a0 >> 14;                  // uniform across the 8 atoms
    const float* __restrict__ base = g_res_logits + (size_t)b * NRES * COUT;

    const float2* src[8];
    #pragma unroll
    for (int j = 0; j < 8; ++j) {
        const int ij = __shfl_sync(0xffffffffu, myv, j);
        src[j] = reinterpret_cast<const float2*>(base + (size_t)ij * COUT);
    }

    if (lane < COUT / 2) {
        float2 x[8];
        #pragma unroll
        for (int j = 0; j < 8; ++j)          // 8 independent L2 loads
            x[j] = src[j][lane];
        float2* __restrict__ d = reinterpret_cast<float2*>(out + (size_t)a0 * COUT);
        #pragma unroll
        for (int j = 0; j < 8; ++j)          // 8 coalesced 200 B stores
            d[lane + 25 * j] = x[j];
    }
}

extern "C" void kernel_launch(void* const* d_in, const int* in_sizes, int n_in,
                              void* d_out, int out_size)
{
    const float* s    = (const float*)d_in[0];  // [B, NRES, CS]
    const float* tta  = (const float*)d_in[1];  // [B, NATOM, NRES]
    const float* W    = (const float*)d_in[2];  // [COUT, CS]
    const float* bias = (const float*)d_in[3];  // [COUT]
    float* out = (float*)d_out;

    (void)in_sizes; (void)n_in; (void)out_size;

    fused_kernel<<<GEMM_BLOCKS + SCAN_BLOCKS, 256>>>(s, tta, W, bias);
    // 32768 atoms / 8 per warp = 4096 warps / 8 per block = 512 blocks
    gather_kernel<<<512, 256>>>(out);
}